// round 1
// baseline (speedup 1.0000x reference)
#include <cuda_runtime.h>
#include <cuda_bf16.h>
#include <cstdint>

#define K  256
#define TT 1024
#define BB 64

// Packed exp(transitions) in bf16: g_ET2[k*K + j] holds rows i=4k..4k+3, column j.
//   .x = bf16(ET[4k][j])   | bf16(ET[4k+1][j]) << 16
//   .y = bf16(ET[4k+2][j]) | bf16(ET[4k+3][j]) << 16
__device__ uint2 g_ET2[(K / 4) * K];   // 16384 * 8B = 128KB
__device__ float g_num[BB];
__device__ float g_den[BB];

// ---------------------------------------------------------------------------
// Pack kernel: ET = exp(transitions), bf16, i-interleaved layout.
// ---------------------------------------------------------------------------
__global__ void pack_kernel(const float* __restrict__ tr) {
    int idx = blockIdx.x * blockDim.x + threadIdx.x;   // 0 .. 16383
    if (idx >= (K / 4) * K) return;
    int k = idx / K;
    int j = idx - k * K;
    int i = 4 * k;
    float e0 = __expf(tr[(i + 0) * K + j]);
    float e1 = __expf(tr[(i + 1) * K + j]);
    float e2 = __expf(tr[(i + 2) * K + j]);
    float e3 = __expf(tr[(i + 3) * K + j]);
    uint32_t p0 = (uint32_t)__bfloat16_as_ushort(__float2bfloat16(e0))
                | ((uint32_t)__bfloat16_as_ushort(__float2bfloat16(e1)) << 16);
    uint32_t p1 = (uint32_t)__bfloat16_as_ushort(__float2bfloat16(e2))
                | ((uint32_t)__bfloat16_as_ushort(__float2bfloat16(e3)) << 16);
    g_ET2[idx] = make_uint2(p0, p1);
}

// ---------------------------------------------------------------------------
// Numerator kernel: one block per batch.
// ---------------------------------------------------------------------------
__global__ void num_kernel(const float* __restrict__ inputs,
                           const long long* __restrict__ tags,
                           const int* __restrict__ mask,
                           const float* __restrict__ tr,
                           const float* __restrict__ starttr,
                           const float* __restrict__ endtr) {
    int b = blockIdx.x;
    int tid = threadIdx.x;                  // 256 threads
    __shared__ float redf[8];
    __shared__ int   redi[8];
    const float* lg = inputs + (size_t)b * TT * K;
    const long long* tg = tags + (size_t)b * TT;

    float partial = 0.0f;
    int lenp = 0;
    for (int t = tid; t < TT; t += 256) {
        int m = mask[b * TT + t];
        lenp += m;
        if (t > 0 && m) {
            int tt = (int)tg[t];
            int tp = (int)tg[t - 1];
            partial += lg[(size_t)t * K + tt] + tr[tp * K + tt];
        }
    }
    #pragma unroll
    for (int o = 16; o; o >>= 1) {
        partial += __shfl_xor_sync(0xFFFFFFFFu, partial, o);
        lenp    += __shfl_xor_sync(0xFFFFFFFFu, lenp, o);
    }
    if ((tid & 31) == 0) { redf[tid >> 5] = partial; redi[tid >> 5] = lenp; }
    __syncthreads();
    if (tid == 0) {
        float s = 0.0f; int len = 0;
        #pragma unroll
        for (int w = 0; w < 8; w++) { s += redf[w]; len += redi[w]; }
        int t0 = (int)tg[0];
        int lastt = (int)tg[len - 1];
        s += lg[t0] + starttr[t0] + endtr[lastt];
        g_num[b] = s;
    }
}

// ---------------------------------------------------------------------------
// Scan kernel: one block (256 threads) per batch. ET in SMEM (bf16 packed).
// Linear-domain forward algorithm with exact 2^-e rescaling each step.
// ---------------------------------------------------------------------------
__device__ __forceinline__ float block_max(float v, float* red) {
    #pragma unroll
    for (int o = 16; o; o >>= 1) v = fmaxf(v, __shfl_xor_sync(0xFFFFFFFFu, v, o));
    if ((threadIdx.x & 31) == 0) red[threadIdx.x >> 5] = v;
    __syncthreads();
    float m = red[0];
    #pragma unroll
    for (int w = 1; w < 8; w++) m = fmaxf(m, red[w]);
    return m;
}

__global__ void __launch_bounds__(256, 1)
scan_kernel(const float* __restrict__ inputs,
            const int* __restrict__ mask,
            const float* __restrict__ starttr,
            const float* __restrict__ endtr) {
    extern __shared__ uint2 smET[];              // 16384 uint2 = 128KB
    __shared__ __align__(16) float p[K];
    __shared__ float red[8];
    __shared__ int   msum[8];
    __shared__ int   maskS[TT];
    __shared__ float endS[K];

    const int b = blockIdx.x;
    const int j = threadIdx.x;

    // Copy ET into SMEM (uint4 = 16B chunks; 8192 total).
    {
        const uint4* src = (const uint4*)g_ET2;
        uint4* dst = (uint4*)smET;
        #pragma unroll
        for (int k = j; k < 8192; k += 256) dst[k] = src[k];
    }

    // Cache mask, compute length.
    int lenp = 0;
    for (int t = j; t < TT; t += 256) {
        int m = mask[b * TT + t];
        maskS[t] = m;
        lenp += m;
    }
    #pragma unroll
    for (int o = 16; o; o >>= 1) lenp += __shfl_xor_sync(0xFFFFFFFFu, lenp, o);
    if ((j & 31) == 0) msum[j >> 5] = lenp;
    float ej = endtr[j];
    endS[j] = __expf(ej);
    __syncthreads();
    int len = 0;
    #pragma unroll
    for (int w = 0; w < 8; w++) len += msum[w];
    const int endidx = len - 1;

    const float* lgbase = inputs + (size_t)b * TT * K;

    // alpha0
    float a = lgbase[j] + starttr[j] + (endidx == 0 ? ej : 0.0f);
    float m0 = block_max(a, red);                // has internal barrier
    p[j] = __expf(a - m0);
    int Eacc = 0;
    __syncthreads();

    float lg = lgbase[K + j];                    // logits at t=1
    const uint2* etcol = smET + j;               // column j, stride K per k
    const float4* p4 = (const float4*)p;

    for (int t = 1; t < TT; t++) {
        float lg_next = (t + 1 < TT) ? lgbase[(size_t)(t + 1) * K + j] : 0.0f;
        if (maskS[t]) {
            float a0 = 0.0f, a1 = 0.0f, a2 = 0.0f, a3 = 0.0f;
            #pragma unroll 8
            for (int k = 0; k < K / 4; k++) {
                uint2 u = etcol[k * K];
                float4 pv = p4[k];
                a0 = fmaf(pv.x, __int_as_float(u.x << 16),          a0);
                a1 = fmaf(pv.y, __int_as_float(u.x & 0xFFFF0000u),  a1);
                a2 = fmaf(pv.z, __int_as_float(u.y << 16),          a2);
                a3 = fmaf(pv.w, __int_as_float(u.y & 0xFFFF0000u),  a3);
            }
            float s = (a0 + a1) + (a2 + a3);
            float q = s * __expf(lg);
            if (t == endidx) q *= endS[j];
            float mq = block_max(q, red);        // barrier: all p-reads done
            int eb = (__float_as_int(mq) >> 23) & 0xFF;
            float scale = __int_as_float((uint32_t)(254 - eb) << 23);  // 2^(127-eb)
            Eacc += eb - 127;
            p[j] = q * scale;
            __syncthreads();                     // p visible for next step
        }
        lg = lg_next;
    }

    // denominator = shift + ln(sum p)
    float v = p[j];
    #pragma unroll
    for (int o = 16; o; o >>= 1) v += __shfl_xor_sync(0xFFFFFFFFu, v, o);
    if ((j & 31) == 0) red[j >> 5] = v;
    __syncthreads();
    if (j == 0) {
        float sum = 0.0f;
        #pragma unroll
        for (int w = 0; w < 8; w++) sum += red[w];
        g_den[b] = m0 + (float)Eacc * 0.6931471805599453f + logf(sum);
    }
}

// ---------------------------------------------------------------------------
// Final reduce: out = sum_b (num_b - den_b)
// ---------------------------------------------------------------------------
__global__ void final_kernel(float* __restrict__ out) {
    int tid = threadIdx.x;                       // 64 threads
    float v = g_num[tid] - g_den[tid];
    #pragma unroll
    for (int o = 16; o; o >>= 1) v += __shfl_xor_sync(0xFFFFFFFFu, v, o);
    __shared__ float r[2];
    if ((tid & 31) == 0) r[tid >> 5] = v;
    __syncthreads();
    if (tid == 0) out[0] = r[0] + r[1];
}

// ---------------------------------------------------------------------------
extern "C" void kernel_launch(void* const* d_in, const int* in_sizes, int n_in,
                              void* d_out, int out_size) {
    const float*     inputs = (const float*)d_in[0];
    const long long* tags   = (const long long*)d_in[1];
    const int*       mask   = (const int*)d_in[2];
    const float*     tr     = (const float*)d_in[3];
    const float*     st     = (const float*)d_in[4];
    const float*     en     = (const float*)d_in[5];
    float* out = (float*)d_out;

    (void)in_sizes; (void)n_in; (void)out_size;

    cudaFuncSetAttribute(scan_kernel, cudaFuncAttributeMaxDynamicSharedMemorySize,
                         (K / 4) * K * (int)sizeof(uint2));

    pack_kernel<<<64, 256>>>(tr);
    num_kernel<<<BB, 256>>>(inputs, tags, mask, tr, st, en);
    scan_kernel<<<BB, 256, (K / 4) * K * sizeof(uint2)>>>(inputs, mask, st, en);
    final_kernel<<<1, 64>>>(out);
}

// round 2
// speedup vs baseline: 2.5443x; 2.5443x over previous
#include <cuda_runtime.h>
#include <cuda_fp16.h>
#include <cstdint>

#define K  256
#define TT 1024
#define BB 64

// Packed exp(transitions) as half2: g_ETh[k*K + j] = (exp(tr[2k][j]), exp(tr[2k+1][j]))
__device__ uint32_t g_ETh[(K / 2) * K];   // 32768 * 4B = 128KB
__device__ float g_num[BB];
__device__ float g_den[BB];

// ---------------------------------------------------------------------------
// Pack kernel: ET = exp(transitions) in half2, i-pair interleaved.
// ---------------------------------------------------------------------------
__global__ void pack_kernel(const float* __restrict__ tr) {
    int idx = blockIdx.x * blockDim.x + threadIdx.x;   // 0 .. 32767
    if (idx >= (K / 2) * K) return;
    int k = idx / K;
    int j = idx - k * K;
    float e0 = __expf(tr[(2 * k + 0) * K + j]);
    float e1 = __expf(tr[(2 * k + 1) * K + j]);
    __half2 h = __floats2half2_rn(e0, e1);
    g_ETh[idx] = *reinterpret_cast<uint32_t*>(&h);
}

// ---------------------------------------------------------------------------
// Numerator kernel: one block per batch.
// ---------------------------------------------------------------------------
__global__ void num_kernel(const float* __restrict__ inputs,
                           const long long* __restrict__ tags,
                           const int* __restrict__ mask,
                           const float* __restrict__ tr,
                           const float* __restrict__ starttr,
                           const float* __restrict__ endtr) {
    int b = blockIdx.x;
    int tid = threadIdx.x;                  // 256 threads
    __shared__ float redf[8];
    __shared__ int   redi[8];
    const float* lg = inputs + (size_t)b * TT * K;
    const long long* tg = tags + (size_t)b * TT;

    float partial = 0.0f;
    int lenp = 0;
    for (int t = tid; t < TT; t += 256) {
        int m = mask[b * TT + t];
        lenp += m;
        if (t > 0 && m) {
            int tt = (int)tg[t];
            int tp = (int)tg[t - 1];
            partial += lg[(size_t)t * K + tt] + tr[tp * K + tt];
        }
    }
    #pragma unroll
    for (int o = 16; o; o >>= 1) {
        partial += __shfl_xor_sync(0xFFFFFFFFu, partial, o);
        lenp    += __shfl_xor_sync(0xFFFFFFFFu, lenp, o);
    }
    if ((tid & 31) == 0) { redf[tid >> 5] = partial; redi[tid >> 5] = lenp; }
    __syncthreads();
    if (tid == 0) {
        float s = 0.0f; int len = 0;
        #pragma unroll
        for (int w = 0; w < 8; w++) { s += redf[w]; len += redi[w]; }
        int t0 = (int)tg[0];
        int lastt = (int)tg[len - 1];
        s += lg[t0] + starttr[t0] + endtr[lastt];
        g_num[b] = s;
    }
}

// ---------------------------------------------------------------------------
// Scan kernel: one block (256 threads) per batch.
// ET column resident in registers (128 half2 per thread). p vector in SMEM
// as fp16. Linear-domain forward pass with exact 2^-e rescaling each step.
// ---------------------------------------------------------------------------
__device__ __forceinline__ __half2 u2h(uint32_t u) {
    return *reinterpret_cast<__half2*>(&u);
}

__global__ void __launch_bounds__(256, 1)
scan_kernel(const float* __restrict__ inputs,
            const int* __restrict__ mask,
            const float* __restrict__ starttr,
            const float* __restrict__ endtr) {
    __shared__ __align__(16) __half p2[K];     // 512B, read via uint4 broadcast
    __shared__ uint32_t wmax[8];
    __shared__ float redf[8];
    __shared__ int   msum[8];
    __shared__ int   maskS[TT];

    const int b = blockIdx.x;
    const int j = threadIdx.x;

    // Load ET column j into registers: 128 half2 (i = 2k, 2k+1), coalesced.
    uint32_t et[K / 2];
    #pragma unroll
    for (int k = 0; k < K / 2; k++) et[k] = g_ETh[k * K + j];

    // Cache mask, compute sequence length.
    int lenp = 0;
    for (int t = j; t < TT; t += 256) {
        int m = mask[b * TT + t];
        maskS[t] = m;
        lenp += m;
    }
    #pragma unroll
    for (int o = 16; o; o >>= 1) lenp += __shfl_xor_sync(0xFFFFFFFFu, lenp, o);
    if ((j & 31) == 0) msum[j >> 5] = lenp;
    float ej = endtr[j];
    float ejExp = __expf(ej);
    __syncthreads();
    int len = 0;
    #pragma unroll
    for (int w = 0; w < 8; w++) len += msum[w];
    const int endidx = len - 1;

    const float* lgbase = inputs + (size_t)b * TT * K;

    // alpha0 (can be negative -> float shuffle max, not integer REDUX)
    float a = lgbase[j] + starttr[j] + (endidx == 0 ? ej : 0.0f);
    {
        float v = a;
        #pragma unroll
        for (int o = 16; o; o >>= 1) v = fmaxf(v, __shfl_xor_sync(0xFFFFFFFFu, v, o));
        if ((j & 31) == 0) redf[j >> 5] = v;
    }
    __syncthreads();
    float m0 = redf[0];
    #pragma unroll
    for (int w = 1; w < 8; w++) m0 = fmaxf(m0, redf[w]);
    p2[j] = __float2half(__expf(a - m0));
    int Eacc = 0;
    __syncthreads();

    float lg = lgbase[K + j];   // logits at t=1

    for (int t = 1; t < TT; t++) {
        float lg_next = (t + 1 < TT) ? lgbase[(size_t)(t + 1) * K + j] : 0.0f;
        if (maskS[t]) {
            // matvec: s_j = sum_i p_i * ET[i][j], chunked fp16->fp32 accumulate
            const uint4* p4 = (const uint4*)p2;   // 16B = 8 halves = 4 half2
            float s = 0.0f;
            #pragma unroll
            for (int c = 0; c < 16; c++) {        // 16 chunks x 16 i's
                uint4 u0 = p4[2 * c];
                uint4 u1 = p4[2 * c + 1];
                __half2 acc = __float2half2_rn(0.0f);
                acc = __hfma2(u2h(et[8 * c + 0]), u2h(u0.x), acc);
                acc = __hfma2(u2h(et[8 * c + 1]), u2h(u0.y), acc);
                acc = __hfma2(u2h(et[8 * c + 2]), u2h(u0.z), acc);
                acc = __hfma2(u2h(et[8 * c + 3]), u2h(u0.w), acc);
                acc = __hfma2(u2h(et[8 * c + 4]), u2h(u1.x), acc);
                acc = __hfma2(u2h(et[8 * c + 5]), u2h(u1.y), acc);
                acc = __hfma2(u2h(et[8 * c + 6]), u2h(u1.z), acc);
                acc = __hfma2(u2h(et[8 * c + 7]), u2h(u1.w), acc);
                float2 f = __half22float2(acc);
                s += f.x + f.y;
            }
            float q = s * __expf(lg);
            if (t == endidx) q *= ejExp;

            // block max of q (q > 0 -> float bits monotonic as uint)
            uint32_t wm = __reduce_max_sync(0xFFFFFFFFu, __float_as_uint(q));
            if ((j & 31) == 0) wmax[j >> 5] = wm;
            __syncthreads();                       // p-reads done; wmax visible
            uint32_t m = wmax[0];
            #pragma unroll
            for (int w = 1; w < 8; w++) m = (m > wmax[w]) ? m : wmax[w];
            int eb = (int)((m >> 23) & 0xFF);
            float scale = __uint_as_float((uint32_t)(254 - eb) << 23);  // 2^(127-eb)
            Eacc += eb - 127;
            p2[j] = __float2half(q * scale);       // max maps to [1,2)
            __syncthreads();                       // p visible for next step
        }
        lg = lg_next;
    }

    // denominator = m0 + Eacc*ln2 + ln(sum p)
    float v = __half2float(p2[j]);
    #pragma unroll
    for (int o = 16; o; o >>= 1) v += __shfl_xor_sync(0xFFFFFFFFu, v, o);
    if ((j & 31) == 0) redf[j >> 5] = v;
    __syncthreads();
    if (j == 0) {
        float sum = 0.0f;
        #pragma unroll
        for (int w = 0; w < 8; w++) sum += redf[w];
        g_den[b] = m0 + (float)Eacc * 0.6931471805599453f + logf(sum);
    }
}

// ---------------------------------------------------------------------------
// Final reduce: out = sum_b (num_b - den_b)
// ---------------------------------------------------------------------------
__global__ void final_kernel(float* __restrict__ out) {
    int tid = threadIdx.x;                       // 64 threads
    float v = g_num[tid] - g_den[tid];
    #pragma unroll
    for (int o = 16; o; o >>= 1) v += __shfl_xor_sync(0xFFFFFFFFu, v, o);
    __shared__ float r[2];
    if ((tid & 31) == 0) r[tid >> 5] = v;
    __syncthreads();
    if (tid == 0) out[0] = r[0] + r[1];
}

// ---------------------------------------------------------------------------
extern "C" void kernel_launch(void* const* d_in, const int* in_sizes, int n_in,
                              void* d_out, int out_size) {
    const float*     inputs = (const float*)d_in[0];
    const long long* tags   = (const long long*)d_in[1];
    const int*       mask   = (const int*)d_in[2];
    const float*     tr     = (const float*)d_in[3];
    const float*     st     = (const float*)d_in[4];
    const float*     en     = (const float*)d_in[5];
    float* out = (float*)d_out;

    (void)in_sizes; (void)n_in; (void)out_size;

    pack_kernel<<<128, 256>>>(tr);
    num_kernel<<<BB, 256>>>(inputs, tags, mask, tr, st, en);
    scan_kernel<<<BB, 256>>>(inputs, mask, st, en);
    final_kernel<<<1, 64>>>(out);
}

// round 3
// speedup vs baseline: 2.7313x; 1.0735x over previous
#include <cuda_runtime.h>
#include <cuda_fp16.h>
#include <cstdint>

#define K  256
#define TT 1024
#define BB 64
#define LN2F 0.6931471805599453f

// ET slices, laid out per (rank, k, tid): thread tid of CTA rank r gets
// half2(exp(tr[i0][j]), exp(tr[i0+1][j])) with h=tid>>7, jl=tid&127,
// j = r*128+jl, i0 = ((r^h)<<7) + 2k.  (h=0 -> own i-half, h=1 -> peer half)
__device__ uint32_t g_ETh[2 * 64 * 256];   // 128KB
__device__ float g_num[BB];
__device__ float g_half[2 * BB];           // per-(batch,rank) log half-sums

// ---------------------------------------------------------------------------
// PTX helpers
// ---------------------------------------------------------------------------
__device__ __forceinline__ uint32_t smem_u32(const void* p) {
    uint32_t a;
    asm("{ .reg .u64 t; cvta.to.shared.u64 t, %1; cvt.u32.u64 %0, t; }"
        : "=r"(a) : "l"(p));
    return a;
}
__device__ __forceinline__ uint32_t mapa_u32(uint32_t a, uint32_t r) {
    uint32_t d;
    asm("mapa.shared::cluster.u32 %0, %1, %2;" : "=r"(d) : "r"(a), "r"(r));
    return d;
}
__device__ __forceinline__ void st_async32(uint32_t raddr, uint32_t v, uint32_t rmbar) {
    asm volatile("st.async.shared::cluster.mbarrier::complete_tx::bytes.b32 [%0], %1, [%2];"
                 :: "r"(raddr), "r"(v), "r"(rmbar) : "memory");
}
__device__ __forceinline__ void mbar_init(uint32_t addr, uint32_t cnt) {
    asm volatile("mbarrier.init.shared.b64 [%0], %1;" :: "r"(addr), "r"(cnt) : "memory");
}
__device__ __forceinline__ void mbar_arm(uint32_t addr, uint32_t bytes) {
    asm volatile("mbarrier.arrive.expect_tx.shared.b64 _, [%0], %1;"
                 :: "r"(addr), "r"(bytes) : "memory");
}
__device__ __forceinline__ void mbar_wait(uint32_t addr, uint32_t parity) {
    asm volatile(
        "{\n\t.reg .pred P;\n\t"
        "WL%=:\n\t"
        "mbarrier.try_wait.parity.acquire.cluster.shared::cta.b64 P, [%0], %1, 0x989680;\n\t"
        "@P bra WD%=;\n\t"
        "bra WL%=;\n\t"
        "WD%=:\n\t}"
        :: "r"(addr), "r"(parity) : "memory");
}
__device__ __forceinline__ void cluster_sync_() {
    asm volatile("barrier.cluster.arrive.aligned;" ::: "memory");
    asm volatile("barrier.cluster.wait.aligned;" ::: "memory");
}
__device__ __forceinline__ uint32_t ctarank_() {
    uint32_t r; asm("mov.u32 %0, %%cluster_ctarank;" : "=r"(r)); return r;
}
__device__ __forceinline__ __half2 u2h(uint32_t u) {
    return *reinterpret_cast<__half2*>(&u);
}

// ---------------------------------------------------------------------------
// Pack kernel
// ---------------------------------------------------------------------------
__global__ void pack_kernel(const float* __restrict__ tr) {
    int idx = blockIdx.x * blockDim.x + threadIdx.x;   // 0..32767
    if (idx >= 2 * 64 * 256) return;
    int r = idx >> 14;
    int rest = idx & 16383;
    int k = rest >> 8;
    int tid = rest & 255;
    int h = tid >> 7;
    int jl = tid & 127;
    int j = (r << 7) + jl;
    int i0 = ((r ^ h) << 7) + 2 * k;
    float e0 = __expf(tr[i0 * K + j]);
    float e1 = __expf(tr[(i0 + 1) * K + j]);
    __half2 hp = __floats2half2_rn(e0, e1);
    g_ETh[idx] = *reinterpret_cast<uint32_t*>(&hp);
}

// ---------------------------------------------------------------------------
// Numerator kernel: one block per batch.
// ---------------------------------------------------------------------------
__global__ void num_kernel(const float* __restrict__ inputs,
                           const long long* __restrict__ tags,
                           const int* __restrict__ mask,
                           const float* __restrict__ tr,
                           const float* __restrict__ starttr,
                           const float* __restrict__ endtr) {
    int b = blockIdx.x;
    int tid = threadIdx.x;
    __shared__ float redf[8];
    __shared__ int   redi[8];
    const float* lg = inputs + (size_t)b * TT * K;
    const long long* tg = tags + (size_t)b * TT;

    float partial = 0.0f;
    int lenp = 0;
    for (int t = tid; t < TT; t += 256) {
        int m = mask[b * TT + t];
        lenp += m;
        if (t > 0 && m) {
            int tt = (int)tg[t];
            int tp = (int)tg[t - 1];
            partial += lg[(size_t)t * K + tt] + tr[tp * K + tt];
        }
    }
    #pragma unroll
    for (int o = 16; o; o >>= 1) {
        partial += __shfl_xor_sync(0xFFFFFFFFu, partial, o);
        lenp    += __shfl_xor_sync(0xFFFFFFFFu, lenp, o);
    }
    if ((tid & 31) == 0) { redf[tid >> 5] = partial; redi[tid >> 5] = lenp; }
    __syncthreads();
    if (tid == 0) {
        float s = 0.0f; int len = 0;
        #pragma unroll
        for (int w = 0; w < 8; w++) { s += redf[w]; len += redi[w]; }
        int t0 = (int)tg[0];
        int lastt = (int)tg[len - 1];
        s += lg[t0] + starttr[t0] + endtr[lastt];
        g_num[b] = s;
    }
}

// ---------------------------------------------------------------------------
// Scan kernel: cluster of 2 CTAs per batch; 256 threads each.
// ---------------------------------------------------------------------------
__global__ void __launch_bounds__(256, 1) __cluster_dims__(2, 1, 1)
scan_kernel(const float* __restrict__ inputs,
            const int* __restrict__ mask,
            const float* __restrict__ starttr,
            const float* __restrict__ endtr) {
    __shared__ __align__(16) __half   pbuf[2][128];       // own-half p, double-buffered
    __shared__ __align__(16) uint32_t rbuf[2][68];        // recv: 64 packed half2 + 4 L floats
    __shared__ __align__(16) float    spart[2][128][4];   // h1 raw block partials
    __shared__ __align__(16) float    Lown[2][4];
    __shared__ __align__(8)  uint64_t mbarF[2];
    __shared__ int   maskS[TT];
    __shared__ float redf[8];
    __shared__ int   msum[8];

    const int tid = threadIdx.x;
    const uint32_t rank = ctarank_();
    const int b  = blockIdx.x >> 1;
    const int h  = tid >> 7;
    const int jl = tid & 127;
    const int jg = ((int)rank << 7) + jl;
    const int w  = (tid >> 5) & 3;         // warp-in-hgroup

    // ET column slice into registers (64 half2)
    uint32_t et[64];
    #pragma unroll
    for (int k = 0; k < 64; k++) et[k] = g_ETh[((int)rank << 14) + (k << 8) + tid];

    // mbarrier init
    if (tid == 0) { mbar_init(smem_u32(&mbarF[0]), 1); mbar_init(smem_u32(&mbarF[1]), 1); }

    // mask + length
    int lenp = 0;
    for (int t = tid; t < TT; t += 256) {
        int m = mask[b * TT + t];
        maskS[t] = m;
        lenp += m;
    }
    #pragma unroll
    for (int o = 16; o; o >>= 1) lenp += __shfl_xor_sync(0xFFFFFFFFu, lenp, o);
    if ((tid & 31) == 0) msum[tid >> 5] = lenp;
    __syncthreads();
    int len = 0;
    #pragma unroll
    for (int q8 = 0; q8 < 8; q8++) len += msum[q8];
    const int endidx = len - 1;

    cluster_sync_();  // mbarriers visible cluster-wide before any st.async

    const uint32_t peer = rank ^ 1u;
    const uint32_t mb_local0 = smem_u32(&mbarF[0]);
    const uint32_t mb_local1 = smem_u32(&mbarF[1]);
    const uint32_t rm_mbar[2]  = { mapa_u32(mb_local0, peer), mapa_u32(mb_local1, peer) };
    const uint32_t rm_rbuf[2]  = { mapa_u32(smem_u32(&rbuf[0][0]), peer),
                                   mapa_u32(smem_u32(&rbuf[1][0]), peer) };

    // Arm both stage barriers for their first completions (272 bytes each).
    if (tid == 128) { mbar_arm(mb_local0, 272); mbar_arm(mb_local1, 272); }

    const float* lgbase = inputs + (size_t)b * TT * K;
    const float  ejExp  = __expf(endtr[jg]);

    float lg = 0.0f, R = 0.0f, partialOwn = 0.0f, phf = 0.0f;

    // ---- Prologue: alpha0, per-warp normalized; state -> stage 1; send ----
    if (h == 0) {
        float a = lgbase[jg] + starttr[jg] + (endidx == 0 ? endtr[jg] : 0.0f);
        float mw = a;
        #pragma unroll
        for (int o = 16; o; o >>= 1) mw = fmaxf(mw, __shfl_xor_sync(0xFFFFFFFFu, mw, o));
        phf = __expf(a - mw);
        __half hp = __float2half(phf);
        pbuf[1][jl] = hp;
        if ((tid & 31) == 0) Lown[1][w] = mw;
        // send packed half2 + L to peer stage 1
        uint32_t hu = (uint32_t)__half_as_ushort(hp);
        uint32_t up = __shfl_down_sync(0xFFFFFFFFu, hu, 1);
        if (!(tid & 1))
            st_async32(rm_rbuf[1] + (uint32_t)(jl >> 1) * 4u, hu | (up << 16), rm_mbar[1]);
        if ((tid & 31) == 0)
            st_async32(rm_rbuf[1] + 256u + (uint32_t)w * 4u, __float_as_uint(mw), rm_mbar[1]);
        lg = lgbase[K + jg];   // prefetch logits t=1
    }
    __syncthreads();           // pbuf[1]/Lown[1] visible

    // ---- Main loop ----
    for (int t = 1; t < TT; t++) {
        const int s = t & 1;
        const int sn = s ^ 1;

        if (h == 1) {
            // X phase (recv half)
            mbar_wait(s ? mb_local1 : mb_local0, (uint32_t)(((t - 1) >> 1) & 1));
            if (tid == 128) mbar_arm(s ? mb_local1 : mb_local0, 272);
            const uint4* p4 = reinterpret_cast<const uint4*>(&rbuf[s][0]);
            float4 pr;
            float* prf = &pr.x;
            #pragma unroll
            for (int wb = 0; wb < 4; wb++) {
                __half2 acc = __float2half2_rn(0.0f);
                #pragma unroll
                for (int c = 0; c < 4; c++) {
                    uint4 u = p4[4 * wb + c];
                    acc = __hfma2(u2h(et[16 * wb + 4 * c + 0]), u2h(u.x), acc);
                    acc = __hfma2(u2h(et[16 * wb + 4 * c + 1]), u2h(u.y), acc);
                    acc = __hfma2(u2h(et[16 * wb + 4 * c + 2]), u2h(u.z), acc);
                    acc = __hfma2(u2h(et[16 * wb + 4 * c + 3]), u2h(u.w), acc);
                }
                float2 f = __half22float2(acc);
                prf[wb] = f.x + f.y;
            }
            *reinterpret_cast<float4*>(&spart[s][jl][0]) = pr;
        } else {
            // X phase (own half) with own block scales
            float4 Lw = *reinterpret_cast<const float4*>(&Lown[s][0]);
            R = fmaxf(fmaxf(Lw.x, Lw.y), fmaxf(Lw.z, Lw.w));
            const uint4* p4 = reinterpret_cast<const uint4*>(&pbuf[s][0]);
            float po = 0.0f;
            const float* Lwf = &Lw.x;
            #pragma unroll
            for (int wb = 0; wb < 4; wb++) {
                __half2 acc = __float2half2_rn(0.0f);
                #pragma unroll
                for (int c = 0; c < 4; c++) {
                    uint4 u = p4[4 * wb + c];
                    acc = __hfma2(u2h(et[16 * wb + 4 * c + 0]), u2h(u.x), acc);
                    acc = __hfma2(u2h(et[16 * wb + 4 * c + 1]), u2h(u.y), acc);
                    acc = __hfma2(u2h(et[16 * wb + 4 * c + 2]), u2h(u.z), acc);
                    acc = __hfma2(u2h(et[16 * wb + 4 * c + 3]), u2h(u.w), acc);
                }
                float2 f = __half22float2(acc);
                po = fmaf(f.x + f.y, __expf(Lwf[wb] - R), po);
            }
            partialOwn = po;
        }

        __syncthreads();  // bar1: spart[s] + rbuf tail readable by h0

        if (h == 0) {
            __half hp;
            float Lnew;
            if (maskS[t]) {
                float4 sp = *reinterpret_cast<const float4*>(&spart[s][jl][0]);
                float4 Lp = *reinterpret_cast<const float4*>(&rbuf[s][64]);
                float sv = partialOwn;
                sv = fmaf(sp.x, __expf(Lp.x - R), sv);
                sv = fmaf(sp.y, __expf(Lp.y - R), sv);
                sv = fmaf(sp.z, __expf(Lp.z - R), sv);
                sv = fmaf(sp.w, __expf(Lp.w - R), sv);
                float q = sv * __expf(lg);
                if (t == endidx) q *= ejExp;
                uint32_t um = __reduce_max_sync(0xFFFFFFFFu, __float_as_uint(q));
                int eb = (int)((um >> 23) & 0xFF);
                float scale = __uint_as_float((uint32_t)(254 - eb) << 23);  // 2^(127-eb)
                Lnew = R + (float)(eb - 127) * LN2F;
                phf = q * scale;
                hp = __float2half(phf);
            } else {
                hp = pbuf[s][jl];
                phf = __half2float(hp);
                Lnew = Lown[s][w];
                __syncwarp();
            }
            pbuf[sn][jl] = hp;
            if ((tid & 31) == 0) Lown[sn][w] = Lnew;
            if (t != TT - 1) {
                uint32_t hu = (uint32_t)__half_as_ushort(hp);
                uint32_t up = __shfl_down_sync(0xFFFFFFFFu, hu, 1);
                if (!(tid & 1))
                    st_async32(rm_rbuf[sn] + (uint32_t)(jl >> 1) * 4u, hu | (up << 16),
                               rm_mbar[sn]);
                if ((tid & 31) == 0)
                    st_async32(rm_rbuf[sn] + 256u + (uint32_t)w * 4u,
                               __float_as_uint(Lnew), rm_mbar[sn]);
            }
            lg = (t + 1 < TT) ? lgbase[(size_t)(t + 1) * K + jg] : 0.0f;
            asm volatile("bar.sync 1, 128;" ::: "memory");   // bar2: h0-only
        }
    }

    // ---- Half-denominator: lnS_r = Rf + ln(sum_w sum_j ph * e^{L_w - Rf}) ----
    __syncthreads();
    if (h == 0) {
        float v = phf;
        #pragma unroll
        for (int o = 16; o; o >>= 1) v += __shfl_xor_sync(0xFFFFFFFFu, v, o);
        if ((tid & 31) == 0) redf[w] = v;
    }
    __syncthreads();
    if (tid == 0) {
        float4 Lw = *reinterpret_cast<const float4*>(&Lown[0][0]);
        float Rf = fmaxf(fmaxf(Lw.x, Lw.y), fmaxf(Lw.z, Lw.w));
        float S = redf[0] * __expf(Lw.x - Rf) + redf[1] * __expf(Lw.y - Rf)
                + redf[2] * __expf(Lw.z - Rf) + redf[3] * __expf(Lw.w - Rf);
        g_half[(b << 1) | (int)rank] = Rf + logf(S);
    }
    cluster_sync_();   // no CTA exits while peer st.async may be in flight
}

// ---------------------------------------------------------------------------
// Final reduce: out = sum_b (num_b - logaddexp(half0, half1))
// ---------------------------------------------------------------------------
__global__ void final_kernel(float* __restrict__ out) {
    int tid = threadIdx.x;                       // 64 threads
    float a0 = g_half[2 * tid];
    float a1 = g_half[2 * tid + 1];
    float mx = fmaxf(a0, a1);
    float den = mx + logf(__expf(a0 - mx) + __expf(a1 - mx));
    float v = g_num[tid] - den;
    #pragma unroll
    for (int o = 16; o; o >>= 1) v += __shfl_xor_sync(0xFFFFFFFFu, v, o);
    __shared__ float r[2];
    if ((tid & 31) == 0) r[tid >> 5] = v;
    __syncthreads();
    if (tid == 0) out[0] = r[0] + r[1];
}

// ---------------------------------------------------------------------------
extern "C" void kernel_launch(void* const* d_in, const int* in_sizes, int n_in,
                              void* d_out, int out_size) {
    const float*     inputs = (const float*)d_in[0];
    const long long* tags   = (const long long*)d_in[1];
    const int*       mask   = (const int*)d_in[2];
    const float*     tr     = (const float*)d_in[3];
    const float*     st     = (const float*)d_in[4];
    const float*     en     = (const float*)d_in[5];
    float* out = (float*)d_out;

    (void)in_sizes; (void)n_in; (void)out_size;

    pack_kernel<<<128, 256>>>(tr);
    num_kernel<<<BB, 256>>>(inputs, tags, mask, tr, st, en);
    scan_kernel<<<2 * BB, 256>>>(inputs, mask, st, en);
    final_kernel<<<1, 64>>>(out);
}

// round 4
// speedup vs baseline: 2.7406x; 1.0034x over previous
#include <cuda_runtime.h>
#include <cuda_fp16.h>
#include <cstdint>

#define K  256
#define TT 1024
#define BB 64
#define LN2F 0.6931471805599453f

// Packed exp(transitions) as half2: g_ETh[k*K + j] = (exp(tr[2k][j]), exp(tr[2k+1][j]))
__device__ uint32_t g_ETh[(K / 2) * K];   // 128KB
__device__ float g_num[BB];
__device__ float g_den[BB];

// ---------------------------------------------------------------------------
__global__ void pack_kernel(const float* __restrict__ tr) {
    int idx = blockIdx.x * blockDim.x + threadIdx.x;   // 0..32767
    if (idx >= (K / 2) * K) return;
    int k = idx / K;
    int j = idx - k * K;
    float e0 = __expf(tr[(2 * k + 0) * K + j]);
    float e1 = __expf(tr[(2 * k + 1) * K + j]);
    __half2 h = __floats2half2_rn(e0, e1);
    g_ETh[idx] = *reinterpret_cast<uint32_t*>(&h);
}

// ---------------------------------------------------------------------------
__global__ void num_kernel(const float* __restrict__ inputs,
                           const long long* __restrict__ tags,
                           const int* __restrict__ mask,
                           const float* __restrict__ tr,
                           const float* __restrict__ starttr,
                           const float* __restrict__ endtr) {
    int b = blockIdx.x;
    int tid = threadIdx.x;
    __shared__ float redf[8];
    __shared__ int   redi[8];
    const float* lg = inputs + (size_t)b * TT * K;
    const long long* tg = tags + (size_t)b * TT;

    float partial = 0.0f;
    int lenp = 0;
    for (int t = tid; t < TT; t += 256) {
        int m = mask[b * TT + t];
        lenp += m;
        if (t > 0 && m) {
            int tt = (int)tg[t];
            int tp = (int)tg[t - 1];
            partial += lg[(size_t)t * K + tt] + tr[tp * K + tt];
        }
    }
    #pragma unroll
    for (int o = 16; o; o >>= 1) {
        partial += __shfl_xor_sync(0xFFFFFFFFu, partial, o);
        lenp    += __shfl_xor_sync(0xFFFFFFFFu, lenp, o);
    }
    if ((tid & 31) == 0) { redf[tid >> 5] = partial; redi[tid >> 5] = lenp; }
    __syncthreads();
    if (tid == 0) {
        float s = 0.0f; int len = 0;
        #pragma unroll
        for (int w = 0; w < 8; w++) { s += redf[w]; len += redi[w]; }
        int t0 = (int)tg[0];
        int lastt = (int)tg[len - 1];
        s += lg[t0] + starttr[t0] + endtr[lastt];
        g_num[b] = s;
    }
}

// ---------------------------------------------------------------------------
// Scan kernel: one block (256 threads) per batch.
// ET column in registers (128 half2/thread). p double-buffered in SMEM (fp16).
// One __syncthreads per step; power-of-2 rescale uses PREVIOUS step's max
// (exact bookkeeping, off the critical path).
// ---------------------------------------------------------------------------
__device__ __forceinline__ __half2 u2h(uint32_t u) {
    return *reinterpret_cast<__half2*>(&u);
}

__global__ void __launch_bounds__(256, 1)
scan_kernel(const float* __restrict__ inputs,
            const int* __restrict__ mask,
            const float* __restrict__ starttr,
            const float* __restrict__ endtr) {
    __shared__ __align__(16) __half    p2[2][K];       // double-buffered, 1KB
    __shared__ __align__(16) uint32_t  wmaxS[2][8];    // per-warp max of stored p (bits)
    __shared__ float redf[8];
    __shared__ int   msum[8];
    __shared__ int   maskS[TT];

    const int b = blockIdx.x;
    const int j = threadIdx.x;
    const int w = j >> 5;

    // ET column j into registers.
    uint32_t et[K / 2];
    #pragma unroll
    for (int k = 0; k < K / 2; k++) et[k] = g_ETh[k * K + j];

    // mask + length
    int lenp = 0;
    for (int t = j; t < TT; t += 256) {
        int m = mask[b * TT + t];
        maskS[t] = m;
        lenp += m;
    }
    #pragma unroll
    for (int o = 16; o; o >>= 1) lenp += __shfl_xor_sync(0xFFFFFFFFu, lenp, o);
    if ((j & 31) == 0) msum[j >> 5] = lenp;
    float ej = endtr[j];
    float ejExp = __expf(ej);
    __syncthreads();
    int len = 0;
    #pragma unroll
    for (int q8 = 0; q8 < 8; q8++) len += msum[q8];
    const int endidx = len - 1;

    const float* lgbase = inputs + (size_t)b * TT * K;

    // ---- alpha0: exact block max, normalized store ----
    float a = lgbase[j] + starttr[j] + (endidx == 0 ? ej : 0.0f);
    {
        float v = a;
        #pragma unroll
        for (int o = 16; o; o >>= 1) v = fmaxf(v, __shfl_xor_sync(0xFFFFFFFFu, v, o));
        if ((j & 31) == 0) redf[j >> 5] = v;
    }
    __syncthreads();
    float m0 = redf[0];
    #pragma unroll
    for (int q8 = 1; q8 < 8; q8++) m0 = fmaxf(m0, redf[q8]);
    float p0 = __expf(a - m0);                     // max = 1.0
    __half hp = __float2half(p0);
    float phf = p0;
    p2[0][j] = hp;
    uint32_t wm = __reduce_max_sync(0xFFFFFFFFu, __float_as_uint(p0));
    if ((j & 31) == 0) wmaxS[0][w] = wm;
    int Eacc = 0;
    __syncthreads();

    // 2-deep logit prefetch
    float lg0 = lgbase[K + j];
    float lg1 = lgbase[2 * K + j];

    int s = 0;
    for (int t = 1; t < TT; t++) {
        const int sn = s ^ 1;

        // Previous step's stored-max (visible after last barrier). Fold later.
        uint4 wa = *reinterpret_cast<const uint4*>(&wmaxS[s][0]);
        uint4 wb = *reinterpret_cast<const uint4*>(&wmaxS[s][4]);

        // matvec: s_j = sum_i p_i * ET[i][j]
        const uint4* p4 = reinterpret_cast<const uint4*>(&p2[s][0]);
        float sv = 0.0f;
        #pragma unroll
        for (int c = 0; c < 16; c++) {
            uint4 u0 = p4[2 * c];
            uint4 u1 = p4[2 * c + 1];
            __half2 acc = __float2half2_rn(0.0f);
            acc = __hfma2(u2h(et[8 * c + 0]), u2h(u0.x), acc);
            acc = __hfma2(u2h(et[8 * c + 1]), u2h(u0.y), acc);
            acc = __hfma2(u2h(et[8 * c + 2]), u2h(u0.z), acc);
            acc = __hfma2(u2h(et[8 * c + 3]), u2h(u0.w), acc);
            acc = __hfma2(u2h(et[8 * c + 4]), u2h(u1.x), acc);
            acc = __hfma2(u2h(et[8 * c + 5]), u2h(u1.y), acc);
            acc = __hfma2(u2h(et[8 * c + 6]), u2h(u1.z), acc);
            acc = __hfma2(u2h(et[8 * c + 7]), u2h(u1.w), acc);
            float2 f = __half22float2(acc);
            sv += f.x + f.y;
        }

        if (maskS[t]) {
            // fold prev max -> scale (exact 2^-c), off matvec critical path
            uint32_t m = wa.x > wa.y ? wa.x : wa.y;
            uint32_t m2 = wa.z > wa.w ? wa.z : wa.w;
            uint32_t m3 = wb.x > wb.y ? wb.x : wb.y;
            uint32_t m4 = wb.z > wb.w ? wb.z : wb.w;
            m = m > m2 ? m : m2; m3 = m3 > m4 ? m3 : m4;
            m = m > m3 ? m : m3;
            int eb = (int)((m >> 23) & 0xFF);
            float scale = __uint_as_float((uint32_t)(254 - eb) << 23);  // 2^(127-eb)
            Eacc += eb - 127;

            float q = sv * __expf(lg0);
            if (t == endidx) q *= ejExp;
            float qs = q * scale;                  // exact
            wm = __reduce_max_sync(0xFFFFFFFFu, __float_as_uint(qs));
            hp = __float2half(qs);
            phf = qs;
        }
        // store (masked step: re-store previous value, carry previous max)
        p2[sn][j] = hp;
        if ((j & 31) == 0) wmaxS[sn][w] = wm;

        // shift prefetch window
        lg0 = lg1;
        lg1 = (t + 2 < TT) ? lgbase[(size_t)(t + 2) * K + j] : 0.0f;

        __syncthreads();
        s = sn;
    }

    // denominator = m0 + Eacc*ln2 + ln(sum stored_T)
    float v = phf;
    #pragma unroll
    for (int o = 16; o; o >>= 1) v += __shfl_xor_sync(0xFFFFFFFFu, v, o);
    if ((j & 31) == 0) redf[j >> 5] = v;
    __syncthreads();
    if (j == 0) {
        float sum = 0.0f;
        #pragma unroll
        for (int q8 = 0; q8 < 8; q8++) sum += redf[q8];
        g_den[b] = m0 + (float)Eacc * LN2F + logf(sum);
    }
}

// ---------------------------------------------------------------------------
__global__ void final_kernel(float* __restrict__ out) {
    int tid = threadIdx.x;                       // 64 threads
    float v = g_num[tid] - g_den[tid];
    #pragma unroll
    for (int o = 16; o; o >>= 1) v += __shfl_xor_sync(0xFFFFFFFFu, v, o);
    __shared__ float r[2];
    if ((tid & 31) == 0) r[tid >> 5] = v;
    __syncthreads();
    if (tid == 0) out[0] = r[0] + r[1];
}

// ---------------------------------------------------------------------------
extern "C" void kernel_launch(void* const* d_in, const int* in_sizes, int n_in,
                              void* d_out, int out_size) {
    const float*     inputs = (const float*)d_in[0];
    const long long* tags   = (const long long*)d_in[1];
    const int*       mask   = (const int*)d_in[2];
    const float*     tr     = (const float*)d_in[3];
    const float*     st     = (const float*)d_in[4];
    const float*     en     = (const float*)d_in[5];
    float* out = (float*)d_out;

    (void)in_sizes; (void)n_in; (void)out_size;

    pack_kernel<<<128, 256>>>(tr);
    num_kernel<<<BB, 256>>>(inputs, tags, mask, tr, st, en);
    scan_kernel<<<BB, 256>>>(inputs, mask, st, en);
    final_kernel<<<1, 64>>>(out);
}